// round 9
// baseline (speedup 1.0000x reference)
#include <cuda_runtime.h>
#include <cuda_bf16.h>
#include <math.h>
#include <cstdint>

static constexpr float EPS32     = 1.1920928955078125e-07f;
static constexpr float MIN_ENORM = 1e-15f;
static constexpr float CLAMP_V   = 16.635532333438687f;  // log(2/eps32)
static constexpr float SMOOTHB   = 50.0f;
static constexpr float MAXNORM   = 1.0f - 1e-5f;
static constexpr float MAXNORM2  = MAXNORM * MAXNORM;

// ---- smem layout (bytes from dynamic-smem base) ----
// A: 64 rows x 136 bf16 (stride 272B). B: 128 rows x 136 bf16.
#define A_HI_OFF   0u
#define A_LO_OFF   17408u
#define B_HI_OFF   34816u
#define B_LO_OFF   69632u
#define VVS_OFF    104448u
#define C_UU_OFF   104704u
#define C_AS_OFF   104960u
#define C_UA_OFF   105216u
#define C_RN_OFF   105472u
#define C_CF_OFF   105728u
#define SMEM_BYTES 105984

__device__ __forceinline__ uint32_t smem_to_u32(const void* smem_ptr) {
    uint32_t addr;
    asm("{ .reg .u64 tmp; cvta.to.shared.u64 tmp, %1; cvt.u32.u64 %0, tmp; }"
        : "=r"(addr) : "l"(smem_ptr));
    return addr;
}

__device__ __forceinline__ void ldsm4(uint32_t addr, uint32_t r[4]) {
    asm volatile("ldmatrix.sync.aligned.m8n8.x4.shared.b16 {%0,%1,%2,%3}, [%4];"
                 : "=r"(r[0]), "=r"(r[1]), "=r"(r[2]), "=r"(r[3]) : "r"(addr));
}

__device__ __forceinline__ void mma16816(float c[4], const uint32_t a[4],
                                         uint32_t b0, uint32_t b1) {
    asm volatile(
        "mma.sync.aligned.m16n8k16.row.col.f32.bf16.bf16.f32 "
        "{%0,%1,%2,%3}, {%4,%5,%6,%7}, {%8,%9}, {%0,%1,%2,%3};"
        : "+f"(c[0]), "+f"(c[1]), "+f"(c[2]), "+f"(c[3])
        : "r"(a[0]), "r"(a[1]), "r"(a[2]), "r"(a[3]), "r"(b0), "r"(b1));
}

// packed split: float4 -> 4 bf16 hi (8B) + 4 bf16 lo (8B), bf16x2 CVTs
__device__ __forceinline__ void store_split8(char* hi, char* lo, uint32_t off, float4 v) {
    uint32_t h01, h23;
    asm("cvt.rn.bf16x2.f32 %0, %1, %2;" : "=r"(h01) : "f"(v.y), "f"(v.x));
    asm("cvt.rn.bf16x2.f32 %0, %1, %2;" : "=r"(h23) : "f"(v.w), "f"(v.z));
    const float fx = __uint_as_float(h01 << 16);
    const float fy = __uint_as_float(h01 & 0xffff0000u);
    const float fz = __uint_as_float(h23 << 16);
    const float fw = __uint_as_float(h23 & 0xffff0000u);
    uint32_t l01, l23;
    asm("cvt.rn.bf16x2.f32 %0, %1, %2;" : "=r"(l01) : "f"(v.y - fy), "f"(v.x - fx));
    asm("cvt.rn.bf16x2.f32 %0, %1, %2;" : "=r"(l23) : "f"(v.w - fw), "f"(v.z - fz));
    uint2 hv, lv;
    hv.x = h01; hv.y = h23;
    lv.x = l01; lv.y = l23;
    *reinterpret_cast<uint2*>(hi + off) = hv;
    *reinterpret_cast<uint2*>(lo + off) = lv;
}

// ---------------- epilogue math: single-divide form ----------------
// arg = lam(sub)*suba*rn = 2*num_s*den*rn / max(d2-num_q, eps*d2); identical algebra.
__device__ __forceinline__ float epilogue(float pv, float wacc, float vv,
                                          float uu, float asc, float ua,
                                          float ranorm, float coef) {
    const float av    = asc * wacc;
    const float alpha = 1.0f - 2.0f * pv + vv;
    const float beta  = 1.0f - uu;
    const float den   = fmaxf(1.0f - 2.0f * pv + uu * vv, EPS32);
    const float d2    = den * den;

    const float num_s = alpha * ua + beta * av;
    const float num_q = alpha * alpha * uu - 2.0f * alpha * beta * pv + beta * beta * vv;

    float arg;
    if (num_q > MAXNORM2 * d2) {
        // rare projection path: ||sub|| clamped to MAXNORM
        const float suba_c = MAXNORM * num_s * __frsqrt_rn(num_q) ;
        const float lam_c  = 2.0f / fmaxf(1.0f - MAXNORM2, EPS32);
        arg = lam_c * suba_c * ranorm;
    } else {
        const float numer = 2.0f * num_s * den * ranorm;
        const float denom = fmaxf(d2 - num_q, EPS32 * d2);
        arg = __fdividef(numer, denom);
    }

    float sc;
    if (fabsf(arg) < 16.0f) {
        sc = arg;  // smooth clamp is identity to <1e-14 here
    } else {
        const float z1  = SMOOTHB * (arg + CLAMP_V);
        const float z2  = SMOOTHB * (arg - CLAMP_V);
        const float sp1 = fmaxf(z1, 0.0f) + log1pf(__expf(-fabsf(z1)));
        const float sp2 = fmaxf(z2, 0.0f) + log1pf(__expf(-fabsf(z2)));
        sc = -CLAMP_V + (sp1 - sp2) * (1.0f / SMOOTHB);
    }

    const float s_ = fabsf(sc);
    const float r  = __logf(s_ + sqrtf(fmaf(s_, s_, 1.0f)));   // asinh(|sc|)
    return coef * copysignf(r, sc);
}

// ---------------- fused kernel ----------------
// grid (2, 64): ob = 64-output slice, bb = 64-batch tile. 512 threads = 16 warps.
// Prologue specialization: threads 0-127 A-split+vv, 128-383 B-split, 384-447 per-o consts.
// Mainloop: warp w -> m-tile (w&3)*16, n-quarter (w>>2)*16 (P and W).
__global__ __launch_bounds__(512, 1)
void hyp_mma_kernel(const float* __restrict__ x,
                    const float* __restrict__ w,
                    const float* __restrict__ p,
                    float* __restrict__ out) {
    extern __shared__ __align__(16) char sm[];
    const uint32_t sbase = smem_to_u32(sm);

    const int tid  = threadIdx.x;
    const int wid  = tid >> 5;
    const int lane = tid & 31;
    const int ob   = blockIdx.x;   // 0..1
    const int bb   = blockIdx.y;   // 0..63

    float* vvs = reinterpret_cast<float*>(sm + VVS_OFF);
    float* cU  = reinterpret_cast<float*>(sm + C_UU_OFF);
    float* cAs = reinterpret_cast<float*>(sm + C_AS_OFF);
    float* cUa = reinterpret_cast<float*>(sm + C_UA_OFF);
    float* cRn = reinterpret_cast<float*>(sm + C_RN_OFF);
    float* cCf = reinterpret_cast<float*>(sm + C_CF_OFF);

    if (tid < 128) {
        // ---- A: x tile [64][128], bf16-split, fused vv ----
        const int row = tid >> 1;        // 0..63
        const int q   = tid & 1;         // 64-col half
        const float* src = x + (size_t)(bb * 64 + row) * 128 + q * 64;
        char* hi = sm + A_HI_OFF;
        char* lo = sm + A_LO_OFF;
        float ss = 0.0f;
#pragma unroll 4
        for (int i = 0; i < 16; i++) {
            float4 v = reinterpret_cast<const float4*>(src)[i];
            ss += v.x * v.x + v.y * v.y + v.z * v.z + v.w * v.w;
            store_split8(hi, lo, (uint32_t)(row * 272 + (q * 64 + i * 4) * 2), v);
        }
        ss += __shfl_xor_sync(0xffffffffu, ss, 1);
        if (q == 0) vvs[row] = ss;
    } else if (tid < 384) {
        // ---- B: [p slice; w slice] [128][128], bf16-split ----
        const int idx = tid - 128;
        const int row = idx >> 1;        // 0..127
        const int q   = idx & 1;
        const float* src = (row < 64)
            ? (p + (size_t)(ob * 64 + row) * 128 + q * 64)
            : (w + (size_t)(ob * 64 + row - 64) * 128 + q * 64);
        char* hi = sm + B_HI_OFF;
        char* lo = sm + B_LO_OFF;
#pragma unroll 4
        for (int i = 0; i < 16; i++) {
            float4 v = reinterpret_cast<const float4*>(src)[i];
            store_split8(hi, lo, (uint32_t)(row * 272 + (q * 64 + i * 4) * 2), v);
        }
    } else if (tid < 448) {
        // ---- per-o constants: one thread per output, full 128-k dots ----
        const int ol = tid - 384;        // 0..63
        const int og = ob * 64 + ol;
        const float4* pr = reinterpret_cast<const float4*>(p + (size_t)og * 128);
        const float4* wr = reinterpret_cast<const float4*>(w + (size_t)og * 128);
        float pp = 0.0f, ww = 0.0f, pw = 0.0f;
#pragma unroll 4
        for (int i = 0; i < 32; i++) {
            float4 a = pr[i], b = wr[i];
            pp += a.x * a.x + a.y * a.y + a.z * a.z + a.w * a.w;
            ww += b.x * b.x + b.y * b.y + b.z * b.z + b.w * b.w;
            pw += a.x * b.x + a.y * b.y + a.z * b.z + a.w * b.w;
        }
        const float uu     = pp;
        const float ascale = fmaxf(1.0f - uu, EPS32);   // 2/lambda_bias
        const float anorm  = fmaxf(ascale * sqrtf(ww), MIN_ENORM);
        cU[ol]  = uu;
        cAs[ol] = ascale;
        cUa[ol] = -ascale * pw;
        cRn[ol] = 1.0f / anorm;
        cCf[ol] = (2.0f / fmaxf(1.0f - uu, EPS32)) * anorm;
    }
    __syncthreads();

    // ---- ldmatrix address prep ----
    const int mt   = wid & 3;              // m-tile (16 rows)
    const int nq   = (wid >> 2) * 16;      // n-quarter (16 outputs)
    const int r8   = (lane & 7) + ((lane >> 3) & 1) * 8;
    const int koff = (lane >> 4) * 8;
    const uint32_t aOff = (uint32_t)((mt * 16 + r8) * 272 + koff * 2);
    const uint32_t bpO  = (uint32_t)((nq + r8) * 272 + koff * 2);
    const uint32_t bwO  = (uint32_t)((nq + 64 + r8) * 272 + koff * 2);

    float accP[2][4], accW[2][4];
#pragma unroll
    for (int j = 0; j < 2; j++)
#pragma unroll
        for (int c = 0; c < 4; c++) { accP[j][c] = 0.0f; accW[j][c] = 0.0f; }

    // ---- mainloop: 3 split terms (hi*hi, hi*lo, lo*hi), 8 k-steps each ----
    // term loop NOT unrolled: fragment registers are reused across terms (no spills).
#pragma unroll 1
    for (int term = 0; term < 3; term++) {
        const uint32_t aBase = sbase + (term == 2 ? A_LO_OFF : A_HI_OFF);
        const uint32_t bBase = sbase + (term == 1 ? B_LO_OFF : B_HI_OFF);
#pragma unroll 4
        for (int ks = 0; ks < 8; ks++) {
            const uint32_t kb = (uint32_t)ks * 32u;
            uint32_t a[4], bp[4], bw4[4];
            ldsm4(aBase + aOff + kb, a);
            ldsm4(bBase + bpO + kb, bp);
            ldsm4(bBase + bwO + kb, bw4);
            mma16816(accP[0], a, bp[0], bp[2]);
            mma16816(accP[1], a, bp[1], bp[3]);
            mma16816(accW[0], a, bw4[0], bw4[2]);
            mma16816(accW[1], a, bw4[1], bw4[3]);
        }
    }

    // ---- epilogue: thread holds D rows m0, m0+8; cols q*2, q*2+1 per n8 tile ----
    {
        const int m0 = mt * 16 + (lane >> 2);
        const int q  = lane & 3;
        const float vv0 = vvs[m0];
        const float vv1 = vvs[m0 + 8];
        const size_t bG0 = (size_t)(bb * 64 + m0) * 128;
        const size_t bG1 = (size_t)(bb * 64 + m0 + 8) * 128;
#pragma unroll
        for (int j = 0; j < 2; j++) {
            const int ol0 = nq + j * 8 + q * 2;
            const int ol1 = ol0 + 1;
            const int og0 = ob * 64 + ol0;
            const float u0 = cU[ol0],  u1 = cU[ol1];
            const float s0 = cAs[ol0], s1 = cAs[ol1];
            const float a0 = cUa[ol0], a1 = cUa[ol1];
            const float r0 = cRn[ol0], r1 = cRn[ol1];
            const float f0 = cCf[ol0], f1 = cCf[ol1];

            float2 e0, e1;
            e0.x = epilogue(accP[j][0], accW[j][0], vv0, u0, s0, a0, r0, f0);
            e0.y = epilogue(accP[j][1], accW[j][1], vv0, u1, s1, a1, r1, f1);
            e1.x = epilogue(accP[j][2], accW[j][2], vv1, u0, s0, a0, r0, f0);
            e1.y = epilogue(accP[j][3], accW[j][3], vv1, u1, s1, a1, r1, f1);

            *reinterpret_cast<float2*>(out + bG0 + og0) = e0;
            *reinterpret_cast<float2*>(out + bG1 + og0) = e1;
        }
    }
}

extern "C" void kernel_launch(void* const* d_in, const int* in_sizes, int n_in,
                              void* d_out, int out_size) {
    const float* x = (const float*)d_in[0];   // [4096, 128]
    const float* w = (const float*)d_in[1];   // [128, 128] weight
    const float* p = (const float*)d_in[2];   // [128, 128] bias
    float* out = (float*)d_out;               // [4096, 128]

    cudaFuncSetAttribute(hyp_mma_kernel,
                         cudaFuncAttributeMaxDynamicSharedMemorySize, SMEM_BYTES);
    dim3 grid(2, 64);
    hyp_mma_kernel<<<grid, 512, SMEM_BYTES>>>(x, w, p, out);
}